// round 2
// baseline (speedup 1.0000x reference)
#include <cuda_runtime.h>
#include <math.h>

// Problem constants
#define T_TOK   2048      // 2*1024 tokens
#define D_MODEL 1024
#define D_FF    4096
#define N_EXP   24
#define N_PAIR  (T_TOK*2) // exactly 4096 token-expert pairs (top-2, distinct)

// GEMM tile config
#define BM 64
#define BN 128
#define BK 16

// -------------------- device scratch (no allocations allowed) ----------------
__device__ int   g_cnt[N_EXP];
__device__ int   g_off[N_EXP];
__device__ int   g_tok_e[N_PAIR];        // expert for (token, k)
__device__ float g_tok_w[N_PAIR];        // softmax gate weight for (token, k)
__device__ int   g_pair_pos[N_PAIR];     // position within expert bucket
__device__ float g_xg[(size_t)N_PAIR * D_MODEL];  // gathered activations (16 MB)
__device__ float g_h [(size_t)N_PAIR * D_FF];     // GELU(x@W1+b1)      (64 MB)
__device__ float g_y [(size_t)N_PAIR * D_MODEL];  // h@W2+b2            (16 MB)

// -------------------- kernels ------------------------------------------------
__global__ void moe_zero() {
    int i = threadIdx.x;
    if (i < N_EXP) g_cnt[i] = 0;
}

// One block per token: scores = x@gate_w + gate_b, top-2, softmax, bucket.
__global__ void moe_gate(const float* __restrict__ x,
                         const float* __restrict__ gw,
                         const float* __restrict__ gb) {
    int t = blockIdx.x;
    __shared__ float xs[D_MODEL];
    __shared__ float part[N_EXP][4];
    __shared__ float scores[N_EXP];

    for (int d = threadIdx.x; d < D_MODEL; d += blockDim.x)
        xs[d] = x[(size_t)t * D_MODEL + d];
    __syncthreads();

    int tid = threadIdx.x;
    if (tid < 96) {
        int e = tid % N_EXP;
        int q = tid / N_EXP;          // 0..3 quarter of D
        float s = 0.f;
        int d0 = q * 256;
        for (int d = d0; d < d0 + 256; ++d)
            s += xs[d] * gw[d * N_EXP + e];
        part[e][q] = s;
    }
    __syncthreads();
    if (tid < N_EXP)
        scores[tid] = part[tid][0] + part[tid][1] + part[tid][2] + part[tid][3] + gb[tid];
    __syncthreads();

    if (tid == 0) {
        // top-2 (first-occurrence tie-break, matches lax.top_k)
        int i0 = 0; float v0 = scores[0];
        for (int e = 1; e < N_EXP; ++e) if (scores[e] > v0) { v0 = scores[e]; i0 = e; }
        int i1 = -1; float v1 = -3.0e38f;
        for (int e = 0; e < N_EXP; ++e) if (e != i0 && scores[e] > v1) { v1 = scores[e]; i1 = e; }
        float g0 = 1.f / (1.f + expf(v1 - v0));  // softmax over {v0,v1}, v0 >= v1
        float g1 = 1.f - g0;

        int p0 = atomicAdd(&g_cnt[i0], 1);
        int p1 = atomicAdd(&g_cnt[i1], 1);
        g_tok_e[2*t]     = i0;  g_tok_e[2*t+1]     = i1;
        g_tok_w[2*t]     = g0;  g_tok_w[2*t+1]     = g1;
        g_pair_pos[2*t]  = p0;  g_pair_pos[2*t+1]  = p1;
    }
}

__global__ void moe_prefix() {
    if (threadIdx.x == 0) {
        int a = 0;
        for (int e = 0; e < N_EXP; ++e) { g_off[e] = a; a += g_cnt[e]; }
    }
}

// Gather x rows into pair-contiguous layout. One block per (token,k).
__global__ void moe_gather(const float* __restrict__ x) {
    int id = blockIdx.x;                 // 0 .. N_PAIR-1 == (t,k)
    int t  = id >> 1;
    int e  = g_tok_e[id];
    int pair = g_off[e] + g_pair_pos[id];
    const float4* src = (const float4*)(x + (size_t)t * D_MODEL);
    float4* dst = (float4*)(g_xg + (size_t)pair * D_MODEL);
    dst[threadIdx.x] = src[threadIdx.x]; // 256 threads * float4 = 1024 floats
}

// Tiled fp32 GEMM over one expert's bucket.
// GELU=true : C=g_h  = gelu( g_xg[M,1024] @ W1e[1024,4096] + b1e )
// GELU=false: C=g_y  =       g_h [M,4096] @ W2e[4096,1024] + b2e
template<int KD, int ND, bool GELU>
__global__ void __launch_bounds__(256)
moe_gemm(const float* __restrict__ Wbase, const float* __restrict__ Bbase) {
    int e   = blockIdx.z;
    int cnt = g_cnt[e];
    int m0  = blockIdx.y * BM;
    if (m0 >= cnt) return;
    int off = g_off[e];
    int n0  = blockIdx.x * BN;

    const float* A = (GELU ? g_xg : g_h) + (size_t)off * KD;
    const float* W = Wbase + (size_t)e * KD * ND;
    float*       C = (GELU ? g_h  : g_y);

    __shared__ float As[BK][BM + 4];
    __shared__ float Bs[BK][BN];

    int tid = threadIdx.x;
    // A tile loaders: 64 rows x 16 cols = 1024 floats, 1 float4/thread
    int ar = tid >> 2;            // 0..63
    int ac = (tid & 3) * 4;       // 0,4,8,12
    // B tile loaders: 16 rows x 128 cols = 2048 floats, 2 float4/thread
    int br = tid >> 5;            // 0..7
    int bc = (tid & 31) * 4;      // 0..124

    int arow = min(m0 + ar, cnt - 1);
    const float* Aptr = A + (size_t)arow * KD + ac;
    const float* Wptr = W + (size_t)br * ND + n0 + bc;

    int tx = tid & 31;            // 32 cols of 4
    int ty = tid >> 5;            // 8 rows of 8

    float acc[8][4] = {};

    for (int k0 = 0; k0 < KD; k0 += BK) {
        float4 av = *(const float4*)(Aptr + k0);
        As[ac + 0][ar] = av.x;
        As[ac + 1][ar] = av.y;
        As[ac + 2][ar] = av.z;
        As[ac + 3][ar] = av.w;
        const float* wp = Wptr + (size_t)k0 * ND;
        *(float4*)&Bs[br][bc]     = *(const float4*)wp;
        *(float4*)&Bs[br + 8][bc] = *(const float4*)(wp + (size_t)8 * ND);
        __syncthreads();

        #pragma unroll
        for (int k = 0; k < BK; ++k) {
            float4 a0 = *(const float4*)&As[k][ty * 8];
            float4 a1 = *(const float4*)&As[k][ty * 8 + 4];
            float4 b0 = *(const float4*)&Bs[k][tx * 4];
            float a[8] = {a0.x, a0.y, a0.z, a0.w, a1.x, a1.y, a1.z, a1.w};
            float b[4] = {b0.x, b0.y, b0.z, b0.w};
            #pragma unroll
            for (int i = 0; i < 8; ++i)
                #pragma unroll
                for (int j = 0; j < 4; ++j)
                    acc[i][j] += a[i] * b[j];
        }
        __syncthreads();
    }

    // epilogue
    #pragma unroll
    for (int i = 0; i < 8; ++i) {
        int m = m0 + ty * 8 + i;
        if (m >= cnt) continue;
        float* crow = C + (size_t)(off + m) * ND + n0;
        #pragma unroll
        for (int j = 0; j < 4; ++j) {
            int n = n0 + tx * 4 + j;
            float v = acc[i][j] + Bbase[e * ND + n];
            if (GELU)
                v = 0.5f * v * (1.f + erff(v * 0.70710678118654752f));
            crow[tx * 4 + j] = v;
        }
    }
}

// out[t] = x[t] + w0*y[pair0] + w1*y[pair1]
__global__ void moe_combine(const float* __restrict__ x, float* __restrict__ out) {
    int t = blockIdx.x;
    int e0 = g_tok_e[2*t], e1 = g_tok_e[2*t+1];
    float w0 = g_tok_w[2*t], w1 = g_tok_w[2*t+1];
    size_t p0 = (size_t)(g_off[e0] + g_pair_pos[2*t])   * D_MODEL;
    size_t p1 = (size_t)(g_off[e1] + g_pair_pos[2*t+1]) * D_MODEL;

    int i = threadIdx.x;  // 256 threads * float4
    const float4* xv = (const float4*)(x + (size_t)t * D_MODEL);
    const float4* y0 = (const float4*)(g_y + p0);
    const float4* y1 = (const float4*)(g_y + p1);
    float4 a = xv[i], c0 = y0[i], c1 = y1[i];
    float4 r;
    r.x = a.x + w0 * c0.x + w1 * c1.x;
    r.y = a.y + w0 * c0.y + w1 * c1.y;
    r.z = a.z + w0 * c0.z + w1 * c1.z;
    r.w = a.w + w0 * c0.w + w1 * c1.w;
    ((float4*)(out + (size_t)t * D_MODEL))[i] = r;
}

// -------------------- launch -------------------------------------------------
extern "C" void kernel_launch(void* const* d_in, const int* in_sizes, int n_in,
                              void* d_out, int out_size) {
    const float* x  = (const float*)d_in[0];
    const float* gw = (const float*)d_in[1];
    const float* gb = (const float*)d_in[2];
    const float* w1 = (const float*)d_in[3];
    const float* b1 = (const float*)d_in[4];
    const float* w2 = (const float*)d_in[5];
    const float* b2 = (const float*)d_in[6];
    float* out = (float*)d_out;

    moe_zero<<<1, 32>>>();
    moe_gate<<<T_TOK, 128>>>(x, gw, gb);
    moe_prefix<<<1, 1>>>();
    moe_gather<<<N_PAIR, 256>>>(x);

    // GEMM1: [M,1024]@[1024,4096], gelu -> g_h
    moe_gemm<D_MODEL, D_FF, true>
        <<<dim3(D_FF / BN, T_TOK / BM, N_EXP), 256>>>(w1, b1);
    // GEMM2: [M,4096]@[4096,1024] -> g_y
    moe_gemm<D_FF, D_MODEL, false>
        <<<dim3(D_MODEL / BN, T_TOK / BM, N_EXP), 256>>>(w2, b2);

    moe_combine<<<T_TOK, 256>>>(x, out);
}

// round 3
// speedup vs baseline: 1.7245x; 1.7245x over previous
#include <cuda_runtime.h>
#include <math.h>

// Problem constants
#define T_TOK   2048
#define D_MODEL 1024
#define D_FF    4096
#define N_EXP   24
#define N_PAIR  (T_TOK*2)

// GEMM tile config (tensor-core version)
#define BM 64
#define BN 128
#define BK 16

// -------------------- device scratch ----------------------------------------
__device__ int   g_cnt[N_EXP];
__device__ int   g_off[N_EXP];
__device__ int   g_tok_e[N_PAIR];
__device__ float g_tok_w[N_PAIR];
__device__ int   g_pair_pos[N_PAIR];
__device__ float g_xg[(size_t)N_PAIR * D_MODEL];
__device__ float g_h [(size_t)N_PAIR * D_FF];
__device__ float g_y [(size_t)N_PAIR * D_MODEL];

// -------------------- small kernels (unchanged) ------------------------------
__global__ void moe_zero() {
    int i = threadIdx.x;
    if (i < N_EXP) g_cnt[i] = 0;
}

__global__ void moe_gate(const float* __restrict__ x,
                         const float* __restrict__ gw,
                         const float* __restrict__ gb) {
    int t = blockIdx.x;
    __shared__ float xs[D_MODEL];
    __shared__ float part[N_EXP][4];
    __shared__ float scores[N_EXP];

    for (int d = threadIdx.x; d < D_MODEL; d += blockDim.x)
        xs[d] = x[(size_t)t * D_MODEL + d];
    __syncthreads();

    int tid = threadIdx.x;
    if (tid < 96) {
        int e = tid % N_EXP;
        int q = tid / N_EXP;
        float s = 0.f;
        int d0 = q * 256;
        for (int d = d0; d < d0 + 256; ++d)
            s += xs[d] * gw[d * N_EXP + e];
        part[e][q] = s;
    }
    __syncthreads();
    if (tid < N_EXP)
        scores[tid] = part[tid][0] + part[tid][1] + part[tid][2] + part[tid][3] + gb[tid];
    __syncthreads();

    if (tid == 0) {
        int i0 = 0; float v0 = scores[0];
        for (int e = 1; e < N_EXP; ++e) if (scores[e] > v0) { v0 = scores[e]; i0 = e; }
        int i1 = -1; float v1 = -3.0e38f;
        for (int e = 0; e < N_EXP; ++e) if (e != i0 && scores[e] > v1) { v1 = scores[e]; i1 = e; }
        float g0 = 1.f / (1.f + expf(v1 - v0));
        float g1 = 1.f - g0;

        int p0 = atomicAdd(&g_cnt[i0], 1);
        int p1 = atomicAdd(&g_cnt[i1], 1);
        g_tok_e[2*t]     = i0;  g_tok_e[2*t+1]     = i1;
        g_tok_w[2*t]     = g0;  g_tok_w[2*t+1]     = g1;
        g_pair_pos[2*t]  = p0;  g_pair_pos[2*t+1]  = p1;
    }
}

__global__ void moe_prefix() {
    if (threadIdx.x == 0) {
        int a = 0;
        for (int e = 0; e < N_EXP; ++e) { g_off[e] = a; a += g_cnt[e]; }
    }
}

__global__ void moe_gather(const float* __restrict__ x) {
    int id = blockIdx.x;
    int t  = id >> 1;
    int e  = g_tok_e[id];
    int pair = g_off[e] + g_pair_pos[id];
    const float4* src = (const float4*)(x + (size_t)t * D_MODEL);
    float4* dst = (float4*)(g_xg + (size_t)pair * D_MODEL);
    dst[threadIdx.x] = src[threadIdx.x];
}

// -------------------- tf32 tensor-core GEMM ----------------------------------
__device__ __forceinline__ unsigned f2tf(float f) {
    unsigned u; asm("cvt.rna.tf32.f32 %0, %1;" : "=r"(u) : "f"(f)); return u;
}

__device__ __forceinline__ void mma_tf32(float* c, const unsigned* a, const unsigned* b) {
    asm volatile(
        "mma.sync.aligned.m16n8k8.row.col.f32.tf32.tf32.f32 "
        "{%0,%1,%2,%3}, {%4,%5,%6,%7}, {%8,%9}, {%0,%1,%2,%3};"
        : "+f"(c[0]), "+f"(c[1]), "+f"(c[2]), "+f"(c[3])
        : "r"(a[0]), "r"(a[1]), "r"(a[2]), "r"(a[3]), "r"(b[0]), "r"(b[1]));
}

// C[M,ND] = (GELU?) ( A[M,KD] @ W_e[KD,ND] + b_e )
// A = g_xg (GELU path) or g_h ; C = g_h or g_y
template<int KD, int ND, bool GELU>
__global__ void __launch_bounds__(256)
moe_gemm_tc(const float* __restrict__ Wbase, const float* __restrict__ Bbase) {
    int e   = blockIdx.z;
    int cnt = g_cnt[e];
    int m0  = blockIdx.y * BM;
    if (m0 >= cnt) return;
    int off = g_off[e];
    int n0  = blockIdx.x * BN;

    const float* A = (GELU ? g_xg : g_h) + (size_t)off * KD;
    const float* W = Wbase + (size_t)e * KD * ND;
    float*       C = (GELU ? g_h  : g_y);

    // As: [m][k] stride 20 (bank-conflict-free frag LDS + aligned STS.128)
    // Bs: [k][n] stride 132
    __shared__ float As[2][BM][BK + 4];
    __shared__ float Bs[2][BK][BN + 4];

    int tid  = threadIdx.x;
    int lane = tid & 31;
    int wid  = tid >> 5;          // 0..7
    int wm   = wid & 1;           // 2 warps along M (32 rows each)
    int wn   = wid >> 1;          // 4 warps along N (32 cols each)
    int g    = lane >> 2;         // 0..7
    int tg   = lane & 3;          // 0..3

    // global-load assignments
    int ar = tid >> 2;            // 0..63  (A row)
    int ac = (tid & 3) * 4;       // 0,4,8,12 (A k)
    int br = tid >> 5;            // 0..7   (B k rows br, br+8)
    int bc = (tid & 31) * 4;      // 0..124 (B n)

    int arow = min(m0 + ar, cnt - 1);
    const float* Aptr = A + (size_t)arow * KD + ac;
    const float* Wptr = W + (size_t)br * ND + n0 + bc;

    float acc[2][4][4] = {};

    // ---- preload tile 0 ----
    float4 av  = *(const float4*)(Aptr);
    float4 bv0 = *(const float4*)(Wptr);
    float4 bv1 = *(const float4*)(Wptr + (size_t)8 * ND);
    {
        float* as = &As[0][ar][ac];
        as[0] = __uint_as_float(f2tf(av.x));
        as[1] = __uint_as_float(f2tf(av.y));
        as[2] = __uint_as_float(f2tf(av.z));
        as[3] = __uint_as_float(f2tf(av.w));
        float4 c0 = make_float4(__uint_as_float(f2tf(bv0.x)), __uint_as_float(f2tf(bv0.y)),
                                __uint_as_float(f2tf(bv0.z)), __uint_as_float(f2tf(bv0.w)));
        float4 c1 = make_float4(__uint_as_float(f2tf(bv1.x)), __uint_as_float(f2tf(bv1.y)),
                                __uint_as_float(f2tf(bv1.z)), __uint_as_float(f2tf(bv1.w)));
        *(float4*)&Bs[0][br][bc]     = c0;
        *(float4*)&Bs[0][br + 8][bc] = c1;
    }
    __syncthreads();

    const int NIT = KD / BK;
    int buf = 0;

    #pragma unroll 1
    for (int it = 0; it < NIT; ++it) {
        // prefetch next tile into registers
        bool more = (it + 1 < NIT);
        if (more) {
            int k0 = (it + 1) * BK;
            av  = *(const float4*)(Aptr + k0);
            const float* wp = Wptr + (size_t)k0 * ND;
            bv0 = *(const float4*)wp;
            bv1 = *(const float4*)(wp + (size_t)8 * ND);
        }

        // ---- compute on current buffer ----
        {
            const float (*as)[BK + 4] = As[buf];
            const float (*bs)[BN + 4] = Bs[buf];
            #pragma unroll
            for (int ks = 0; ks < 2; ++ks) {
                int k0 = ks * 8;
                unsigned a[2][4], b[4][2];
                #pragma unroll
                for (int mi = 0; mi < 2; ++mi) {
                    int m = wm * 32 + mi * 16;
                    a[mi][0] = __float_as_uint(as[m + g    ][k0 + tg]);
                    a[mi][1] = __float_as_uint(as[m + g + 8][k0 + tg]);
                    a[mi][2] = __float_as_uint(as[m + g    ][k0 + tg + 4]);
                    a[mi][3] = __float_as_uint(as[m + g + 8][k0 + tg + 4]);
                }
                #pragma unroll
                for (int ni = 0; ni < 4; ++ni) {
                    int n = wn * 32 + ni * 8;
                    b[ni][0] = __float_as_uint(bs[k0 + tg    ][n + g]);
                    b[ni][1] = __float_as_uint(bs[k0 + tg + 4][n + g]);
                }
                #pragma unroll
                for (int mi = 0; mi < 2; ++mi)
                    #pragma unroll
                    for (int ni = 0; ni < 4; ++ni)
                        mma_tf32(acc[mi][ni], a[mi], b[ni]);
            }
        }

        // ---- stage next tile into other buffer ----
        if (more) {
            int nb = buf ^ 1;
            float* as = &As[nb][ar][ac];
            as[0] = __uint_as_float(f2tf(av.x));
            as[1] = __uint_as_float(f2tf(av.y));
            as[2] = __uint_as_float(f2tf(av.z));
            as[3] = __uint_as_float(f2tf(av.w));
            float4 c0 = make_float4(__uint_as_float(f2tf(bv0.x)), __uint_as_float(f2tf(bv0.y)),
                                    __uint_as_float(f2tf(bv0.z)), __uint_as_float(f2tf(bv0.w)));
            float4 c1 = make_float4(__uint_as_float(f2tf(bv1.x)), __uint_as_float(f2tf(bv1.y)),
                                    __uint_as_float(f2tf(bv1.z)), __uint_as_float(f2tf(bv1.w)));
            *(float4*)&Bs[nb][br][bc]     = c0;
            *(float4*)&Bs[nb][br + 8][bc] = c1;
            __syncthreads();
            buf = nb;
        }
    }

    // ---- epilogue ----
    #pragma unroll
    for (int mi = 0; mi < 2; ++mi) {
        #pragma unroll
        for (int ni = 0; ni < 4; ++ni) {
            int nc = n0 + wn * 32 + ni * 8 + 2 * tg;
            float bb0 = Bbase[e * ND + nc];
            float bb1 = Bbase[e * ND + nc + 1];
            #pragma unroll
            for (int h = 0; h < 2; ++h) {
                int m = m0 + wm * 32 + mi * 16 + g + 8 * h;
                if (m >= cnt) continue;
                float v0 = acc[mi][ni][2 * h]     + bb0;
                float v1 = acc[mi][ni][2 * h + 1] + bb1;
                if (GELU) {
                    v0 = 0.5f * v0 * (1.f + erff(v0 * 0.70710678118654752f));
                    v1 = 0.5f * v1 * (1.f + erff(v1 * 0.70710678118654752f));
                }
                float2 r = make_float2(v0, v1);
                *(float2*)(C + (size_t)(off + m) * ND + nc) = r;
            }
        }
    }
}

// -------------------- combine ------------------------------------------------
__global__ void moe_combine(const float* __restrict__ x, float* __restrict__ out) {
    int t = blockIdx.x;
    int e0 = g_tok_e[2*t], e1 = g_tok_e[2*t+1];
    float w0 = g_tok_w[2*t], w1 = g_tok_w[2*t+1];
    size_t p0 = (size_t)(g_off[e0] + g_pair_pos[2*t])   * D_MODEL;
    size_t p1 = (size_t)(g_off[e1] + g_pair_pos[2*t+1]) * D_MODEL;

    int i = threadIdx.x;
    const float4* xv = (const float4*)(x + (size_t)t * D_MODEL);
    const float4* y0 = (const float4*)(g_y + p0);
    const float4* y1 = (const float4*)(g_y + p1);
    float4 a = xv[i], c0 = y0[i], c1 = y1[i];
    float4 r;
    r.x = a.x + w0 * c0.x + w1 * c1.x;
    r.y = a.y + w0 * c0.y + w1 * c1.y;
    r.z = a.z + w0 * c0.z + w1 * c1.z;
    r.w = a.w + w0 * c0.w + w1 * c1.w;
    ((float4*)(out + (size_t)t * D_MODEL))[i] = r;
}

// -------------------- launch -------------------------------------------------
extern "C" void kernel_launch(void* const* d_in, const int* in_sizes, int n_in,
                              void* d_out, int out_size) {
    const float* x  = (const float*)d_in[0];
    const float* gw = (const float*)d_in[1];
    const float* gb = (const float*)d_in[2];
    const float* w1 = (const float*)d_in[3];
    const float* b1 = (const float*)d_in[4];
    const float* w2 = (const float*)d_in[5];
    const float* b2 = (const float*)d_in[6];
    float* out = (float*)d_out;

    moe_zero<<<1, 32>>>();
    moe_gate<<<T_TOK, 128>>>(x, gw, gb);
    moe_prefix<<<1, 1>>>();
    moe_gather<<<N_PAIR, 256>>>(x);

    moe_gemm_tc<D_MODEL, D_FF, true>
        <<<dim3(D_FF / BN, T_TOK / BM, N_EXP), 256>>>(w1, b1);
    moe_gemm_tc<D_FF, D_MODEL, false>
        <<<dim3(D_MODEL / BN, T_TOK / BM, N_EXP), 256>>>(w2, b2);

    moe_combine<<<T_TOK, 256>>>(x, out);
}